// round 14
// baseline (speedup 1.0000x reference)
#include <cuda_runtime.h>

// Grid_nd_sample: bilinear interpolation gather. (R12-best body, persistent)
// in_tensor: (B=16, H=128, W=128, C=256) fp32 (268 MB)
// indices:   (B, P=8192, 2) fp32
// out:       (B, P, C) fp32 (134 MB)
//
// Converged design (10-round map): 2 points/thread, 8 front-batched
// independent 16B gathers, 256-thr blocks, .cs streaming stores.
// This round: persistent grid-stride launch (1184 CTAs = 148 SMs x 8)
// removes the ~14 wave boundaries of the one-shot 16384-CTA grid and
// lets loads of iteration i+1 overlap the tail of iteration i.

namespace {
constexpr int B = 16;
constexpr int H = 128;
constexpr int W = 128;
constexpr int C = 256;
constexpr int P = 8192;
constexpr int C4 = C / 4;                       // 64 float4 chunks per point
constexpr long NPAIR = (long)B * P / 2;         // 65536 point-pairs
constexpr long TOTAL = NPAIR * C4;              // 4,194,304 work items
constexpr int NSM = 148;
constexpr int CTAS = NSM * 8;                   // 1184 persistent CTAs
}

__global__ __launch_bounds__(256) void grid_sample_kernel(
    const float* __restrict__ in,
    const float* __restrict__ idx,
    float* __restrict__ out)
{
    const long stride = (long)gridDim.x * blockDim.x;   // 303104
    for (long i = (long)blockIdx.x * blockDim.x + threadIdx.x;
         i < TOTAL; i += stride)
    {
        int  c4   = (int)(i & (C4 - 1));   // 0..63
        long pair = i >> 6;                // pair id
        long bp0  = pair * 2;
        long bp1  = bp0 + 1;
        int  b    = (int)(bp0 >> 13);      // P = 2^13; pair never spans images

        // Index loads: warp-uniform (32 lanes share one pair) -> broadcast
        float4 ii = __ldg((const float4*)(idx + bp0 * 2));  // {y0,x0,y1,x1}
        float iy0 = ii.x, ix0 = ii.y, iy1 = ii.z, ix1 = ii.w;

        // Point 0 coords/weights
        float fy0 = floorf(iy0), fx0 = floorf(ix0);
        int ay0 = (int)fy0, ax0 = (int)fx0;
        int by0 = (int)ceilf(iy0), bx0 = (int)ceilf(ix0);
        float muy0 = iy0 - fy0, mux0 = ix0 - fx0;

        // Point 1 coords/weights
        float fy1 = floorf(iy1), fx1 = floorf(ix1);
        int ay1 = (int)fy1, ax1 = (int)fx1;
        int by1 = (int)ceilf(iy1), bx1 = (int)ceilf(ix1);
        float muy1 = iy1 - fy1, mux1 = ix1 - fx1;

        const long img = (long)b * H * W * C;
        const float4* base = (const float4*)(in + img);

        // 8 independent gathers, front-batched for max MLP
        const float4* p0r00 = base + (((long)ay0 * W + ax0) * C4) + c4;
        const float4* p0r10 = base + (((long)by0 * W + ax0) * C4) + c4;
        const float4* p0r01 = base + (((long)ay0 * W + bx0) * C4) + c4;
        const float4* p0r11 = base + (((long)by0 * W + bx0) * C4) + c4;
        const float4* p1r00 = base + (((long)ay1 * W + ax1) * C4) + c4;
        const float4* p1r10 = base + (((long)by1 * W + ax1) * C4) + c4;
        const float4* p1r01 = base + (((long)ay1 * W + bx1) * C4) + c4;
        const float4* p1r11 = base + (((long)by1 * W + bx1) * C4) + c4;

        float4 a0 = __ldg(p0r00);
        float4 b0 = __ldg(p0r10);
        float4 c0 = __ldg(p0r01);
        float4 d0 = __ldg(p0r11);
        float4 a1 = __ldg(p1r00);
        float4 b1 = __ldg(p1r10);
        float4 c1 = __ldg(p1r01);
        float4 d1 = __ldg(p1r11);

        float w00a = (1.0f - muy0) * (1.0f - mux0);
        float w10a = muy0 * (1.0f - mux0);
        float w01a = (1.0f - muy0) * mux0;
        float w11a = muy0 * mux0;

        float w00b = (1.0f - muy1) * (1.0f - mux1);
        float w10b = muy1 * (1.0f - mux1);
        float w01b = (1.0f - muy1) * mux1;
        float w11b = muy1 * mux1;

        float4 o0, o1;
        o0.x = a0.x * w00a + b0.x * w10a + c0.x * w01a + d0.x * w11a;
        o0.y = a0.y * w00a + b0.y * w10a + c0.y * w01a + d0.y * w11a;
        o0.z = a0.z * w00a + b0.z * w10a + c0.z * w01a + d0.z * w11a;
        o0.w = a0.w * w00a + b0.w * w10a + c0.w * w01a + d0.w * w11a;

        o1.x = a1.x * w00b + b1.x * w10b + c1.x * w01b + d1.x * w11b;
        o1.y = a1.y * w00b + b1.y * w10b + c1.y * w01b + d1.y * w11b;
        o1.z = a1.z * w00b + b1.z * w10b + c1.z * w01b + d1.z * w11b;
        o1.w = a1.w * w00b + b1.w * w10b + c1.w * w01b + d1.w * w11b;

        __stcs(((float4*)(out + bp0 * C)) + c4, o0);
        __stcs(((float4*)(out + bp1 * C)) + c4, o1);
    }
}

extern "C" void kernel_launch(void* const* d_in, const int* in_sizes, int n_in,
                              void* d_out, int out_size)
{
    const float* in_tensor = (const float*)d_in[0];
    const float* indices   = (const float*)d_in[1];
    float* out = (float*)d_out;

    grid_sample_kernel<<<CTAS, 256>>>(in_tensor, indices, out);
}

// round 15
// speedup vs baseline: 1.4043x; 1.4043x over previous
#include <cuda_runtime.h>

// Grid_nd_sample: bilinear interpolation gather. (FINAL — converged R12)
// in_tensor: (B=16, H=128, W=128, C=256) fp32 (268 MB)
// indices:   (B, P=8192, 2) fp32
// out:       (B, P, C) fp32 (134 MB)
//
// Design space exhaustively mapped over 13 rounds:
//  - 2 points/thread, 8 front-batched independent 16B gathers
//    (4 and 16 loads/thread both regress)
//  - 256-thread blocks (256 > 512 > 1024)
//  - one-shot 16384-CTA grid (persistent grid-stride regresses: breaks
//    L2 co-residency of adjacent pairs; sorting regresses: localizing
//    reads randomizes writes)
//  - streaming .cs stores (keeps write-once output out of L2 reuse window)
//  - exact-divisible grid, no bounds guard
// Kernel sits at the compulsory DRAM traffic floor (~334 MB) AND the
// random-read + streaming-write mix bandwidth ceiling (~75% of 8 TB/s).

namespace {
constexpr int B = 16;
constexpr int H = 128;
constexpr int W = 128;
constexpr int C = 256;
constexpr int P = 8192;
constexpr int C4 = C / 4;                       // 64 float4 chunks per point
constexpr long NPAIR = (long)B * P / 2;         // 65536 point-pairs
constexpr long TOTAL = NPAIR * C4;              // 4,194,304 threads (=16384*256)
}

__global__ __launch_bounds__(256) void grid_sample_kernel(
    const float* __restrict__ in,
    const float* __restrict__ idx,
    float* __restrict__ out)
{
    long i = (long)blockIdx.x * blockDim.x + threadIdx.x;

    int  c4   = (int)(i & (C4 - 1));   // 0..63
    long pair = i >> 6;                // pair id
    long bp0  = pair * 2;
    long bp1  = bp0 + 1;
    int  b    = (int)(bp0 >> 13);      // P = 8192 = 2^13; pair never spans images

    // Index loads: warp-uniform (all 32 lanes share one pair) -> broadcast
    float4 ii = __ldg((const float4*)(idx + bp0 * 2));  // {y0, x0, y1, x1}
    float iy0 = ii.x, ix0 = ii.y, iy1 = ii.z, ix1 = ii.w;

    // Point 0 coords/weights
    float fy0 = floorf(iy0), fx0 = floorf(ix0);
    int ay0 = (int)fy0, ax0 = (int)fx0;
    int by0 = (int)ceilf(iy0), bx0 = (int)ceilf(ix0);
    float muy0 = iy0 - fy0, mux0 = ix0 - fx0;

    // Point 1 coords/weights
    float fy1 = floorf(iy1), fx1 = floorf(ix1);
    int ay1 = (int)fy1, ax1 = (int)fx1;
    int by1 = (int)ceilf(iy1), bx1 = (int)ceilf(ix1);
    float muy1 = iy1 - fy1, mux1 = ix1 - fx1;

    const long img = (long)b * H * W * C;
    const float4* base = (const float4*)(in + img);

    // 8 independent gathers, front-batched for max MLP
    const float4* p0r00 = base + (((long)ay0 * W + ax0) * C4) + c4;
    const float4* p0r10 = base + (((long)by0 * W + ax0) * C4) + c4;
    const float4* p0r01 = base + (((long)ay0 * W + bx0) * C4) + c4;
    const float4* p0r11 = base + (((long)by0 * W + bx0) * C4) + c4;
    const float4* p1r00 = base + (((long)ay1 * W + ax1) * C4) + c4;
    const float4* p1r10 = base + (((long)by1 * W + ax1) * C4) + c4;
    const float4* p1r01 = base + (((long)ay1 * W + bx1) * C4) + c4;
    const float4* p1r11 = base + (((long)by1 * W + bx1) * C4) + c4;

    float4 a0 = __ldg(p0r00);
    float4 b0 = __ldg(p0r10);
    float4 c0 = __ldg(p0r01);
    float4 d0 = __ldg(p0r11);
    float4 a1 = __ldg(p1r00);
    float4 b1 = __ldg(p1r10);
    float4 c1 = __ldg(p1r01);
    float4 d1 = __ldg(p1r11);

    float w00a = (1.0f - muy0) * (1.0f - mux0);
    float w10a = muy0 * (1.0f - mux0);
    float w01a = (1.0f - muy0) * mux0;
    float w11a = muy0 * mux0;

    float w00b = (1.0f - muy1) * (1.0f - mux1);
    float w10b = muy1 * (1.0f - mux1);
    float w01b = (1.0f - muy1) * mux1;
    float w11b = muy1 * mux1;

    float4 o0, o1;
    o0.x = a0.x * w00a + b0.x * w10a + c0.x * w01a + d0.x * w11a;
    o0.y = a0.y * w00a + b0.y * w10a + c0.y * w01a + d0.y * w11a;
    o0.z = a0.z * w00a + b0.z * w10a + c0.z * w01a + d0.z * w11a;
    o0.w = a0.w * w00a + b0.w * w10a + c0.w * w01a + d0.w * w11a;

    o1.x = a1.x * w00b + b1.x * w10b + c1.x * w01b + d1.x * w11b;
    o1.y = a1.y * w00b + b1.y * w10b + c1.y * w01b + d1.y * w11b;
    o1.z = a1.z * w00b + b1.z * w10b + c1.z * w01b + d1.z * w11b;
    o1.w = a1.w * w00b + b1.w * w10b + c1.w * w01b + d1.w * w11b;

    __stcs(((float4*)(out + bp0 * C)) + c4, o0);
    __stcs(((float4*)(out + bp1 * C)) + c4, o1);
}

extern "C" void kernel_launch(void* const* d_in, const int* in_sizes, int n_in,
                              void* d_out, int out_size)
{
    const float* in_tensor = (const float*)d_in[0];
    const float* indices   = (const float*)d_in[1];
    float* out = (float*)d_out;

    const int threads = 256;
    const long blocks = TOTAL / threads;  // 16384, exact
    grid_sample_kernel<<<(unsigned)blocks, threads>>>(in_tensor, indices, out);
}